// round 7
// baseline (speedup 1.0000x reference)
#include <cuda_runtime.h>
#include <math.h>
#include <float.h>

#define Bq   1024
#define Dd   1024
#define Nn   65536
#define Mm   8
#define KS   256
#define DSs  128
#define OUTn 2048
#define KTOP 64

// ---------------- static device scratch (no dynamic allocation) ----------------
__device__ float g_q[Bq * Dd];                 // 4 MB : q = x @ W
__device__ float g_lut[Bq * Mm * KS];          // 8 MB : lut[b][m][c] = c_sq - 2*cross
__device__ float g_csq[Mm * KS];               // 8 KB
__device__ unsigned long long g_codes[Nn];     // 512 KB : 8 packed u8 codes per n

// ---------------- K0: pack key_codes (N x 8 int32) -> u64 per n ----------------
__global__ void pack_codes_k(const int* __restrict__ kc) {
    int n = blockIdx.x * blockDim.x + threadIdx.x;   // grid exactly N
    unsigned long long v = 0;
#pragma unroll
    for (int m = 0; m < 8; m++)
        v |= (unsigned long long)((unsigned)kc[n * 8 + m] & 255u) << (8 * m);
    g_codes[n] = v;
}

// ---------------- K0b: c_sq[m][c] = ||codebook[m][c]||^2 ----------------
__global__ void csq_k(const float* __restrict__ cb) {
    int g = blockIdx.x * blockDim.x + threadIdx.x;   // 2048 warps exactly
    int w = g >> 5, lane = g & 31;
    const float* r = cb + w * DSs;
    float s = 0.f;
#pragma unroll
    for (int d = lane; d < DSs; d += 32) { float x = r[d]; s = fmaf(x, x, s); }
#pragma unroll
    for (int o = 16; o; o >>= 1) s += __shfl_xor_sync(0xffffffffu, s, o);
    if (lane == 0) g_csq[w] = s;
}

// ---------------- K1: q = x @ W   (fp32, 128x64 tiles, BK=32) ----------------
__global__ void __launch_bounds__(256) gemm_k(const float* __restrict__ A,
                                              const float* __restrict__ W) {
    __shared__ float As[32][128];
    __shared__ float Bs[32][64];
    int m0 = blockIdx.y * 128;
    int n0 = blockIdx.x * 64;
    int tid = threadIdx.x;
    int tx = tid & 15;
    int ty = tid >> 4;
    float acc[8][4];
#pragma unroll
    for (int i = 0; i < 8; i++)
#pragma unroll
        for (int j = 0; j < 4; j++) acc[i][j] = 0.f;

    for (int k0 = 0; k0 < Dd; k0 += 32) {
#pragma unroll
        for (int p = 0; p < 4; p++) {
            int l = (p * 256 + tid) * 4;
            int r = l >> 5, c = l & 31;
            float4 v = *(const float4*)&A[(m0 + r) * Dd + k0 + c];
            As[c + 0][r] = v.x; As[c + 1][r] = v.y;
            As[c + 2][r] = v.z; As[c + 3][r] = v.w;
        }
#pragma unroll
        for (int p = 0; p < 2; p++) {
            int l = (p * 256 + tid) * 4;
            int r = l >> 6, c = l & 63;
            *(float4*)&Bs[r][c] = *(const float4*)&W[(k0 + r) * Dd + n0 + c];
        }
        __syncthreads();
#pragma unroll
        for (int kk = 0; kk < 32; kk++) {
            float ra[8], rb[4];
            *(float4*)&ra[0] = *(float4*)&As[kk][ty * 8];
            *(float4*)&ra[4] = *(float4*)&As[kk][ty * 8 + 4];
            *(float4*)&rb[0] = *(float4*)&Bs[kk][tx * 4];
#pragma unroll
            for (int i = 0; i < 8; i++)
#pragma unroll
                for (int j = 0; j < 4; j++) acc[i][j] = fmaf(ra[i], rb[j], acc[i][j]);
        }
        __syncthreads();
    }
#pragma unroll
    for (int i = 0; i < 8; i++) {
        float4 v = make_float4(acc[i][0], acc[i][1], acc[i][2], acc[i][3]);
        *(float4*)&g_q[(m0 + ty * 8 + i) * Dd + n0 + tx * 4] = v;
    }
}

// ---------------- K2: lut[b][m][c] = csq[m][c] - 2 * dot(q[b][m*128:], cb[m][c]) ----------------
__global__ void __launch_bounds__(256) lut_k(const float* __restrict__ cb) {
    int m  = blockIdx.z;
    int b0 = blockIdx.y * 64;
    int c0 = blockIdx.x * 64;
    __shared__ float Qs[32][64];   // [d][b]
    __shared__ float Cs[32][64];   // [d][c]
    int tid = threadIdx.x;
    int tx = tid & 15, ty = tid >> 4;
    float acc[4][4];
#pragma unroll
    for (int i = 0; i < 4; i++)
#pragma unroll
        for (int j = 0; j < 4; j++) acc[i][j] = 0.f;

    const float* cbm = cb + m * KS * DSs;
    for (int k0 = 0; k0 < DSs; k0 += 32) {
#pragma unroll
        for (int p = 0; p < 2; p++) {
            int l = (p * 256 + tid) * 4;
            int r = l >> 5, c = l & 31;
            float4 v = *(const float4*)&g_q[(b0 + r) * Dd + m * DSs + k0 + c];
            Qs[c + 0][r] = v.x; Qs[c + 1][r] = v.y;
            Qs[c + 2][r] = v.z; Qs[c + 3][r] = v.w;
            float4 u = *(const float4*)&cbm[(c0 + r) * DSs + k0 + c];
            Cs[c + 0][r] = u.x; Cs[c + 1][r] = u.y;
            Cs[c + 2][r] = u.z; Cs[c + 3][r] = u.w;
        }
        __syncthreads();
#pragma unroll
        for (int kk = 0; kk < 32; kk++) {
            float ra[4], rb[4];
            *(float4*)&ra[0] = *(float4*)&Qs[kk][ty * 4];
            *(float4*)&rb[0] = *(float4*)&Cs[kk][tx * 4];
#pragma unroll
            for (int i = 0; i < 4; i++)
#pragma unroll
                for (int j = 0; j < 4; j++) acc[i][j] = fmaf(ra[i], rb[j], acc[i][j]);
        }
        __syncthreads();
    }
#pragma unroll
    for (int i = 0; i < 4; i++) {
        int bb = b0 + ty * 4 + i;
        int cc = c0 + tx * 4;
        float4 s4 = *(const float4*)&g_csq[m * KS + cc];
        float4 v = make_float4(s4.x - 2.f * acc[i][0],
                               s4.y - 2.f * acc[i][1],
                               s4.z - 2.f * acc[i][2],
                               s4.w - 2.f * acc[i][3]);
        *(float4*)&g_lut[bb * OUTn + m * KS + cc] = v;
    }
}

// ---------------- bitonic prune: sort 1024 (dist,idx) ascending, keep 64 ----------------
__device__ void prune512(float* cd, int* ci, int* s_count, float* s_tau, int tid) {
    int cnt = *s_count;
#pragma unroll
    for (int i = tid; i < 1024; i += 512)
        if (i >= cnt) { cd[i] = FLT_MAX; ci[i] = 0; }
    __syncthreads();
#pragma unroll 1
    for (int k = 2; k <= 1024; k <<= 1) {
#pragma unroll 1
        for (int j = k >> 1; j > 0; j >>= 1) {
            int idx = ((tid & ~(j - 1)) << 1) | (tid & (j - 1));
            int ixj = idx | j;
            bool up = ((idx & k) == 0);
            float a = cd[idx], bv = cd[ixj];
            bool sw = up ? (bv < a) : (a < bv);
            if (sw) {
                int ia = ci[idx];
                cd[idx] = bv; cd[ixj] = a;
                ci[idx] = ci[ixj]; ci[ixj] = ia;
            }
            __syncthreads();
        }
    }
    if (tid == 0) { *s_count = KTOP; *s_tau = cd[KTOP - 1]; }
    __syncthreads();
}

// ---------------- K3: PQ scan + online top-64 + softmax + value gather ----------------
__global__ void __launch_bounds__(512) scan_k(const int* __restrict__ vcodes,
                                              const float* __restrict__ vcb,
                                              const float* __restrict__ bias,
                                              float* __restrict__ out) {
    int b = blockIdx.x;
    int tid = threadIdx.x;
    __shared__ float lut_s[2048];
    __shared__ float cd[1024];
    __shared__ int   ci[1024];
    __shared__ int   s_count;
    __shared__ float s_tau;
    __shared__ float s_w[KTOP];
    __shared__ float s_winv;

    // stage LUT (8 KB) into smem
    ((float4*)lut_s)[tid] = ((const float4*)&g_lut[b * 2048])[tid];
    if (tid == 0) { s_count = 0; s_tau = FLT_MAX; }
    __syncthreads();

    // scan 65536 codes, 128 iterations of 512
#pragma unroll 1
    for (int it = 0; it < Nn / 512; ++it) {
        int n = (it << 9) + tid;
        unsigned long long c8 = g_codes[n];
        unsigned lo = (unsigned)c8;
        unsigned hi = (unsigned)(c8 >> 32);
        float d;
        d  = lut_s[          (lo         & 255u)];
        d += lut_s[ 256 + ((lo >>  8) & 255u)];
        d += lut_s[ 512 + ((lo >> 16) & 255u)];
        d += lut_s[ 768 +  (lo >> 24)         ];
        d += lut_s[1024 + ( hi         & 255u)];
        d += lut_s[1280 + ((hi >>  8) & 255u)];
        d += lut_s[1536 + ((hi >> 16) & 255u)];
        d += lut_s[1792 +  (hi >> 24)         ];
        if (d < s_tau) {
            int p = atomicAdd(&s_count, 1);
            cd[p] = d; ci[p] = n;
        }
        __syncthreads();
        if (s_count > 512) prune512(cd, ci, &s_count, &s_tau, tid);
    }
    prune512(cd, ci, &s_count, &s_tau, tid);   // final: cd[0..63] ascending dists

    // softmax over -dist (q_sq shift cancels; shift by d0 = max of -dist)
    float d0 = cd[0];
    if (tid < KTOP) s_w[tid] = expf(d0 - cd[tid]);
    __syncthreads();
    if (tid == 0) {
        float s = 0.f;
        for (int i = 0; i < KTOP; i++) s += s_w[i];
        s_winv = 1.0f / s;
    }
    __syncthreads();

    // y[b, o] = bias[o] + sum_k w_k * vcb[mv][value_codes[n_k][mv]][dv], o = mv*256+dv
    int o0   = tid << 2;          // 4 outputs per thread (512*4 = 2048)
    int mv   = o0 >> 8;           // warp-uniform
    int col4 = (o0 & 255) >> 2;
    float4 acc = *(const float4*)&bias[o0];
    const float4* vcb4 = (const float4*)vcb;
    float winv = s_winv;
#pragma unroll 4
    for (int kk = 0; kk < KTOP; kk++) {
        int n = ci[kk];
        float w = s_w[kk] * winv;
        int code = vcodes[n * 8 + mv];
        float4 v = vcb4[(((mv << 8) + code) << 6) + col4];
        acc.x = fmaf(w, v.x, acc.x);
        acc.y = fmaf(w, v.y, acc.y);
        acc.z = fmaf(w, v.z, acc.z);
        acc.w = fmaf(w, v.w, acc.w);
    }
    *(float4*)&out[b * OUTn + o0] = acc;
}

// ---------------- launch ----------------
extern "C" void kernel_launch(void* const* d_in, const int* in_sizes, int n_in,
                              void* d_out, int out_size) {
    const float* x    = (const float*)d_in[0];   // (B, D)
    const float* W    = (const float*)d_in[1];   // (D, D)
    const float* kcb  = (const float*)d_in[2];   // (M, Ks, DS)
    const float* vcb  = (const float*)d_in[3];   // (MV, Ks, DV)
    const float* bias = (const float*)d_in[4];   // (OUT,)
    const int*   kc   = (const int*)d_in[5];     // (N, M)
    const int*   vc   = (const int*)d_in[6];     // (N, MV)
    float* out = (float*)d_out;                  // (B, OUT)

    pack_codes_k<<<Nn / 256, 256>>>(kc);
    csq_k<<<(Mm * KS * 32) / 256, 256>>>(kcb);
    gemm_k<<<dim3(Dd / 64, Bq / 128), 256>>>(x, W);
    lut_k<<<dim3(KS / 64, Bq / 64, Mm), 256>>>(kcb);
    scan_k<<<Bq, 512>>>(vc, vcb, bias, out);
}